// round 1
// baseline (speedup 1.0000x reference)
#include <cuda_runtime.h>

#define TT 512
#define IN 64
#define HH 16
#define G4 64   /* 4*H */
#define NC 6
#define NB 1024

__device__ __forceinline__ float fast_tanh(float x) {
    float r;
    asm("tanh.approx.f32 %0, %1;" : "=f"(r) : "f"(x));
    return r;
}
__device__ __forceinline__ float fast_sig(float x) {
    // sigmoid(x) = 0.5 * tanh(0.5 x) + 0.5
    return fmaf(fast_tanh(0.5f * x), 0.5f, 0.5f);
}

__global__ __launch_bounds__(64, 8)
void lstm_fused_kernel(const float* __restrict__ x,
                       const float* __restrict__ w_ih,
                       const float* __restrict__ w_hh,
                       const float* __restrict__ b_ih,
                       const float* __restrict__ b_hh,
                       const float* __restrict__ w_fc,
                       const float* __restrict__ b_fc,
                       float* __restrict__ out)
{
    const int b = blockIdx.x;
    const int g = threadIdx.x;  // 0..63, one gate per thread

    __shared__ __align__(16) float s_x[IN];
    __shared__ __align__(16) float s_h[HH];
    __shared__ __align__(16) float s_gate[G4];
    __shared__ float s_fc[HH][NC];

    // ---- weights in registers (same for every block -> L1/L2 hits) ----
    float4 wi[16];
    {
        const float4* p = (const float4*)(w_ih + g * IN);
        #pragma unroll
        for (int k = 0; k < 16; k++) wi[k] = p[k];
    }
    float4 wh[4];
    {
        const float4* p = (const float4*)(w_hh + g * HH);
        #pragma unroll
        for (int k = 0; k < 4; k++) wh[k] = p[k];
    }
    const float bias = b_ih[g] + b_hh[g];

    if (g < HH) s_h[g] = 0.0f;
    float c = 0.0f;
    float accfc[NC];
    #pragma unroll
    for (int k = 0; k < NC; k++) accfc[k] = 0.0f;

    const float* xb = x + (size_t)b * TT * IN;
    float x_reg = xb[g];  // prefetch t=0

    for (int t = 0; t < TT; t++) {
        s_x[g] = x_reg;
        __syncthreads();  // (A) s_x[t] and s_h[t-1] visible

        // prefetch next timestep's x element (latency hidden by FMA body)
        if (t + 1 < TT) x_reg = xb[(t + 1) * IN + g];

        // gate_g = bias + dot(w_ih[g,:], x_t) + dot(w_hh[g,:], h_{t-1})
        float a0 = bias, a1 = 0.0f, a2 = 0.0f, a3 = 0.0f;
        const float4* xs = (const float4*)s_x;
        #pragma unroll
        for (int k = 0; k < 16; k++) {
            float4 xv = xs[k];  // broadcast LDS.128
            a0 = fmaf(wi[k].x, xv.x, a0);
            a1 = fmaf(wi[k].y, xv.y, a1);
            a2 = fmaf(wi[k].z, xv.z, a2);
            a3 = fmaf(wi[k].w, xv.w, a3);
        }
        const float4* hs = (const float4*)s_h;
        #pragma unroll
        for (int k = 0; k < 4; k++) {
            float4 hv = hs[k];  // broadcast LDS.128
            a0 = fmaf(wh[k].x, hv.x, a0);
            a1 = fmaf(wh[k].y, hv.y, a1);
            a2 = fmaf(wh[k].z, hv.z, a2);
            a3 = fmaf(wh[k].w, hv.w, a3);
        }
        s_gate[g] = (a0 + a1) + (a2 + a3);
        __syncthreads();  // (B) gates ready; s_x/s_h reads of step t done

        if (g < HH) {
            float gi = s_gate[g];
            float gf = s_gate[g + HH];
            float gg = s_gate[g + 2 * HH];
            float go = s_gate[g + 3 * HH];
            c = fast_sig(gf) * c + fast_sig(gi) * fast_tanh(gg);
            float h = fast_sig(go) * fast_tanh(c);
            s_h[g] = h;  // consumed after barrier (A) of step t+1

            // fused FC accumulation: out[b,cls] += h_t[g] * w_fc[cls, t*16+g]
            const float* wf = w_fc + t * HH + g;
            #pragma unroll
            for (int cls = 0; cls < NC; cls++)
                accfc[cls] = fmaf(h, __ldg(wf + cls * (TT * HH)), accfc[cls]);
        }
    }

    __syncthreads();
    if (g < HH) {
        #pragma unroll
        for (int cls = 0; cls < NC; cls++) s_fc[g][cls] = accfc[cls];
    }
    __syncthreads();
    if (g < NC) {
        float s = b_fc[g];
        #pragma unroll
        for (int j = 0; j < HH; j++) s += s_fc[j][g];
        out[b * NC + g] = s;
    }
}

extern "C" void kernel_launch(void* const* d_in, const int* in_sizes, int n_in,
                              void* d_out, int out_size) {
    const float* x    = (const float*)d_in[0];
    const float* w_ih = (const float*)d_in[1];
    const float* w_hh = (const float*)d_in[2];
    const float* b_ih = (const float*)d_in[3];
    const float* b_hh = (const float*)d_in[4];
    const float* w_fc = (const float*)d_in[5];
    const float* b_fc = (const float*)d_in[6];
    float* out = (float*)d_out;

    lstm_fused_kernel<<<NB, 64>>>(x, w_ih, w_hh, b_ih, b_hh, w_fc, b_fc, out);
}

// round 3
// speedup vs baseline: 1.4818x; 1.4818x over previous
#include <cuda_runtime.h>

#define TT 512
#define IN 64
#define HH 16
#define NC 6
#define NB 1024

typedef unsigned long long u64;

__device__ __forceinline__ float fast_tanh(float x) {
    float r; asm("tanh.approx.f32 %0, %1;" : "=f"(r) : "f"(x)); return r;
}
__device__ __forceinline__ float fast_sig(float x) {
    return fmaf(fast_tanh(0.5f * x), 0.5f, 0.5f);
}
// packed fp32x2 FMA (sm_100+): acc = w*x + acc on two packed floats
__device__ __forceinline__ void ffma2(u64& a, u64 b, u64 c) {
    asm("fma.rn.f32x2 %0, %1, %2, %0;" : "+l"(a) : "l"(b), "l"(c));
}
__device__ __forceinline__ u64 fadd2(u64 a, u64 b) {
    u64 r; asm("add.rn.f32x2 %0, %1, %2;" : "=l"(r) : "l"(a), "l"(b)); return r;
}
__device__ __forceinline__ float2 upk(u64 v) {
    float2 r; asm("mov.b64 {%0, %1}, %2;" : "=f"(r.x), "=f"(r.y) : "l"(v)); return r;
}
__device__ __forceinline__ u64 pk(float x, float y) {
    u64 r; asm("mov.b64 %0, {%1, %2};" : "=l"(r) : "f"(x), "f"(y)); return r;
}

// One warp per batch element. lane owns gates glo=lane and ghi=lane+32.
// Gate order [i,f,g,o]x16: lanes 0..15 -> (i_j, g_j), lanes 16..31 -> (f_j, o_j).
__global__ __launch_bounds__(32, 8)
void lstm_warp_kernel(const float* __restrict__ x,
                      const float* __restrict__ w_ih,
                      const float* __restrict__ w_hh,
                      const float* __restrict__ b_ih,
                      const float* __restrict__ b_hh,
                      const float* __restrict__ w_fc,
                      const float* __restrict__ b_fc,
                      float* __restrict__ out)
{
    const int b    = blockIdx.x;
    const int lane = threadIdx.x;
    const int glo  = lane;
    const int ghi  = lane + 32;

    __shared__ __align__(16) u64   s_x2[IN / 2];  // x_t, packed pairs
    __shared__ __align__(16) float s_h[HH];

    // ---- weights in registers (packed pairs along k) ----
    u64 wlo[IN / 2], whi[IN / 2], hlo[HH / 2], hhi[HH / 2];
    {
        const ulonglong2* p = (const ulonglong2*)(w_ih + glo * IN);
        #pragma unroll
        for (int k = 0; k < IN / 4; k++) { ulonglong2 v = p[k]; wlo[2*k] = v.x; wlo[2*k+1] = v.y; }
        p = (const ulonglong2*)(w_ih + ghi * IN);
        #pragma unroll
        for (int k = 0; k < IN / 4; k++) { ulonglong2 v = p[k]; whi[2*k] = v.x; whi[2*k+1] = v.y; }
        p = (const ulonglong2*)(w_hh + glo * HH);
        #pragma unroll
        for (int k = 0; k < HH / 4; k++) { ulonglong2 v = p[k]; hlo[2*k] = v.x; hlo[2*k+1] = v.y; }
        p = (const ulonglong2*)(w_hh + ghi * HH);
        #pragma unroll
        for (int k = 0; k < HH / 4; k++) { ulonglong2 v = p[k]; hhi[2*k] = v.x; hhi[2*k+1] = v.y; }
    }
    const float bias_lo = b_ih[glo] + b_hh[glo];
    const float bias_hi = b_ih[ghi] + b_hh[ghi];

    if (lane < HH) s_h[lane] = 0.0f;
    float c = 0.0f;
    float afc0 = 0.0f, afc1 = 0.0f, afc2 = 0.0f;

    // FC pointers: lanes 0..15 handle classes 0..2 for hidden j=lane,
    //              lanes 16..31 handle classes 3..5 for hidden j=lane-16.
    const float* wf0 = w_fc + (size_t)(lane >> 4) * 3 * (TT * HH) + (lane & 15);
    const float* wf1 = wf0 + (size_t)(TT * HH);
    const float* wf2 = wf0 + (size_t)(2 * TT * HH);

    const float* xb = x + (size_t)b * TT * IN;
    // depth-2 prefetch of this lane's packed x pair
    u64 xcur = *(const u64*)(xb + 2 * lane);
    u64 xnxt = *(const u64*)(xb + IN + 2 * lane);

    for (int t = 0; t < TT; t++) {
        s_x2[lane] = xcur;
        __syncwarp();              // x_t and h_{t-1} visible to whole warp
        xcur = xnxt;
        if (t + 2 < TT) xnxt = *(const u64*)(xb + (t + 2) * IN + 2 * lane);

        // FC weight loads issued early (L2/L1-resident; batched for MLP)
        const int to = t * HH;
        float wfa = wf0[to], wfb = wf1[to], wfc_ = wf2[to];

        u64 alo0 = pk(bias_lo, 0.0f), alo1 = 0ull;
        u64 ahi0 = pk(bias_hi, 0.0f), ahi1 = 0ull;

        const ulonglong2* xs = (const ulonglong2*)s_x2;
        #pragma unroll
        for (int k = 0; k < IN / 4; k++) {
            ulonglong2 xv = xs[k];            // broadcast LDS.128 = 2 packed pairs
            ffma2(alo0, wlo[2*k],   xv.x);
            ffma2(alo1, wlo[2*k+1], xv.y);
            ffma2(ahi0, whi[2*k],   xv.x);
            ffma2(ahi1, whi[2*k+1], xv.y);
        }
        const ulonglong2* hs = (const ulonglong2*)s_h;
        #pragma unroll
        for (int k = 0; k < HH / 4; k++) {
            ulonglong2 hv = hs[k];
            ffma2(alo0, hlo[2*k],   hv.x);
            ffma2(alo1, hlo[2*k+1], hv.y);
            ffma2(ahi0, hhi[2*k],   hv.x);
            ffma2(ahi1, hhi[2*k+1], hv.y);
        }
        float2 plo = upk(fadd2(alo0, alo1));
        float2 phi = upk(fadd2(ahi0, ahi1));
        float v_lo = plo.x + plo.y;   // i_j (lane<16) | f_j (lane>=16)
        float v_hi = phi.x + phi.y;   // g_j (lane<16) | o_j (lane>=16)

        // fetch f_j, o_j from partner lane j+16 (shfl also orders the warp:
        // all lanes' shared reads of step t complete before s_h is rewritten)
        float fg = __shfl_sync(0xffffffffu, v_lo, (lane + 16) & 31);
        float og = __shfl_sync(0xffffffffu, v_hi, (lane + 16) & 31);

        float h = 0.0f;
        if (lane < HH) {
            c = fast_sig(fg) * c + fast_sig(v_lo) * fast_tanh(v_hi);
            h = fast_sig(og) * fast_tanh(c);
            s_h[lane] = h;            // read next iter after __syncwarp
        }
        // broadcast h_j to partner lane for the FC split
        float hsh = __shfl_sync(0xffffffffu, h, lane & 15);

        afc0 = fmaf(hsh, wfa,  afc0);
        afc1 = fmaf(hsh, wfb,  afc1);
        afc2 = fmaf(hsh, wfc_, afc2);
    }

    // reduce FC partials over the 16 hidden units within each half-warp
    #pragma unroll
    for (int off = 8; off >= 1; off >>= 1) {
        afc0 += __shfl_xor_sync(0xffffffffu, afc0, off);
        afc1 += __shfl_xor_sync(0xffffffffu, afc1, off);
        afc2 += __shfl_xor_sync(0xffffffffu, afc2, off);
    }
    if (lane == 0) {
        out[b * NC + 0] = afc0 + b_fc[0];
        out[b * NC + 1] = afc1 + b_fc[1];
        out[b * NC + 2] = afc2 + b_fc[2];
    } else if (lane == 16) {
        out[b * NC + 3] = afc0 + b_fc[3];
        out[b * NC + 4] = afc1 + b_fc[4];
        out[b * NC + 5] = afc2 + b_fc[5];
    }
}

extern "C" void kernel_launch(void* const* d_in, const int* in_sizes, int n_in,
                              void* d_out, int out_size) {
    const float* x    = (const float*)d_in[0];
    const float* w_ih = (const float*)d_in[1];
    const float* w_hh = (const float*)d_in[2];
    const float* b_ih = (const float*)d_in[3];
    const float* b_hh = (const float*)d_in[4];
    const float* w_fc = (const float*)d_in[5];
    const float* b_fc = (const float*)d_in[6];
    float* out = (float*)d_out;

    lstm_warp_kernel<<<NB, 32>>>(x, w_ih, w_hh, b_ih, b_hh, w_fc, b_fc, out);
}